// round 11
// baseline (speedup 1.0000x reference)
#include <cuda_runtime.h>
#include <cuda_bf16.h>
#include <cstdint>

// ---------------- problem dims ----------------
#define BATCH    512
#define ZI       16
#define TT       8
#define DD       128
#define IMG_ROWS (BATCH*ZI)   // 8192 img vectors
#define TXT_ROWS (BATCH*TT)   // 4096 text vectors

// GEMM: C[txt][img] ; CTA tile: M = 128 txt rows, N = 256 img rows, K = 128
#define TILE_M   128
#define TILE_N   256
#define MT_TILES  (TXT_ROWS/TILE_M)   // 32
#define NT2_TILES (IMG_ROWS/TILE_N)   // 32

#define NTHREADS 512                  // 16 warps: 2 (M) x 8 (N)
// per-warp tile: 64 (M) x 32 (N) -> 4 mtiles (m16) x 4 ntiles (n8), acc = 64 fp32 regs

// smem: row = 128 bf16 = 256 B, padded stride 272 B (68 banks -> lane bank
// (4g+t4)%32, all distinct -> conflict-free fragment loads)
#define SROW     272
#define SMEM_A_OFF 0                       // text tile: 128 rows
#define SMEM_B_OFF (128*SROW)              // img tile:  256 rows
#define SMEM_TILES ((128+256)*SROW)        // 104448 B

// ---------------- scratch (device globals; no allocation allowed) ----------------
__device__ __align__(16) __nv_bfloat16 g_imgn [IMG_ROWS*DD];   // 2 MB
__device__ __align__(16) __nv_bfloat16 g_textn[TXT_ROWS*DD];   // 1 MB
__device__ float  g_Q[NT2_TILES*TXT_ROWS];  // den_t2i partials: [nt2][txt]  512 KB
__device__ float  g_P[MT_TILES*BATCH];      // den_i2t partials: [mt][bi]    64 KB
__device__ float  g_diag[TXT_ROWS];         // S[b,b,t] at txt=b*8+t         16 KB
__device__ double g_part[MT_TILES];         // per-CTA partial loss sums     256 B

// ---------------- helpers ----------------
__device__ __forceinline__ uint32_t smem_u32(const void* p) {
    uint32_t a;
    asm("{ .reg .u64 tmp; cvta.to.shared.u64 tmp, %1; cvt.u32.u64 %0, tmp; }"
        : "=r"(a) : "l"(p));
    return a;
}
// cp.async 16B, L2-only (.cg) — sm_80 base PTX, valid at .target sm_103
#define CP_ASYNC16(saddr, gptr) \
    asm volatile("cp.async.cg.shared.global [%0], [%1], 16;" \
        :: "r"(saddr), "l"(__cvta_generic_to_global(gptr)) : "memory")
#define CP_ASYNC_COMMIT() asm volatile("cp.async.commit_group;" ::: "memory")
#define CP_ASYNC_WAIT(n)  asm volatile("cp.async.wait_group %0;" :: "n"(n) : "memory")

// ---------------- kernel 1: L2-normalize rows, write bf16 ----------------
__global__ __launch_bounds__(256)
void norm_kernel(const float* __restrict__ img, const float* __restrict__ text)
{
    int gw   = (blockIdx.x * blockDim.x + threadIdx.x) >> 5;  // global warp = row
    int lane = threadIdx.x & 31;
    if (gw >= IMG_ROWS + TXT_ROWS) return;

    const float* src;
    __nv_bfloat16* dst;
    if (gw < IMG_ROWS) { src = img  + (size_t)gw * DD;            dst = g_imgn  + (size_t)gw * DD; }
    else               { src = text + (size_t)(gw - IMG_ROWS)*DD; dst = g_textn + (size_t)(gw - IMG_ROWS)*DD; }

    float4 v = reinterpret_cast<const float4*>(src)[lane];
    float ss = v.x*v.x + v.y*v.y + v.z*v.z + v.w*v.w;
    #pragma unroll
    for (int off = 16; off >= 1; off >>= 1)
        ss += __shfl_xor_sync(0xffffffffu, ss, off);
    float inv = 1.0f / fmaxf(sqrtf(ss), 1e-12f);

    __nv_bfloat162 p0 = __floats2bfloat162_rn(v.x * inv, v.y * inv);
    __nv_bfloat162 p1 = __floats2bfloat162_rn(v.z * inv, v.w * inv);
    reinterpret_cast<__nv_bfloat162*>(dst)[2*lane + 0] = p0;
    reinterpret_cast<__nv_bfloat162*>(dst)[2*lane + 1] = p1;
}

// ---------------- bf16 warp MMA: m16n8k16, row.col, fp32 acc ----------------
__device__ __forceinline__ void mma_16816(float* c, uint32_t a0, uint32_t a1,
                                          uint32_t a2, uint32_t a3,
                                          uint32_t b0, uint32_t b1)
{
    asm volatile(
        "mma.sync.aligned.m16n8k16.row.col.f32.bf16.bf16.f32 "
        "{%0,%1,%2,%3}, {%4,%5,%6,%7}, {%8,%9}, {%0,%1,%2,%3};\n"
        : "+f"(c[0]), "+f"(c[1]), "+f"(c[2]), "+f"(c[3])
        : "r"(a0), "r"(a1), "r"(a2), "r"(a3), "r"(b0), "r"(b1));
}

// 4 K-steps (64 bf16 of K) starting at byte offset kbase within each row
__device__ __forceinline__ void gemm_4ksteps(float (*acc)[4][4],
                                             const char* aw, const char* bw, int kbase)
{
    #pragma unroll
    for (int ks = 0; ks < 4; ++ks) {
        const int ko = kbase + ks * 32;          // 16 bf16 = 32 bytes per K-step
        uint32_t b0[4], b1[4];
        #pragma unroll
        for (int nt = 0; nt < 4; ++nt) {
            const char* p = bw + nt * 8 * SROW + ko;
            b0[nt] = *reinterpret_cast<const uint32_t*>(p);
            b1[nt] = *reinterpret_cast<const uint32_t*>(p + 16);
        }
        #pragma unroll
        for (int mtl = 0; mtl < 4; ++mtl) {
            const char* p = aw + mtl * 16 * SROW + ko;
            uint32_t a0 = *reinterpret_cast<const uint32_t*>(p);
            uint32_t a1 = *reinterpret_cast<const uint32_t*>(p + 8 * SROW);
            uint32_t a2 = *reinterpret_cast<const uint32_t*>(p + 16);
            uint32_t a3 = *reinterpret_cast<const uint32_t*>(p + 8 * SROW + 16);
            #pragma unroll
            for (int nt = 0; nt < 4; ++nt)
                mma_16816(acc[mtl][nt], a0, a1, a2, a3, b0[nt], b1[nt]);
        }
    }
}

// ---------------- kernel 2: fused GEMM (HMMA) + max/exp/reduce epilogue ----------------
__global__ __launch_bounds__(NTHREADS)
void gemm_epilogue_kernel()
{
    extern __shared__ char smem[];
    char* sA = smem + SMEM_A_OFF;
    char* sB = smem + SMEM_B_OFF;
    __shared__ float red_q[8][128];   // [warp_n][local txt row] partial den_t2i
    __shared__ float red_p[16][2];    // [local bi][warp_m] partial den_i2t

    const int tid  = threadIdx.x;
    const int wid  = tid >> 5;
    const int lane = tid & 31;
    const int g    = lane >> 2;       // 0..7
    const int t4   = lane & 3;        // 0..3
    const int warp_m = wid >> 3;      // 0..1  (64-row half)
    const int warp_n = wid & 7;       // 0..7  (32-col slice = 2 bi-groups)
    const int nt2 = blockIdx.x;       // img tile  [0,32)
    const int mt  = blockIdx.y;       // text tile [0,32)

    const __nv_bfloat16* gA = g_textn + (size_t)(TILE_M * mt) * DD;
    const __nv_bfloat16* gB = g_imgn  + (size_t)(TILE_N * nt2) * DD;
    const uint32_t sAu = smem_u32(sA);
    const uint32_t sBu = smem_u32(sB);

    // ---- stage 0: K cols [0,64) (chunks 0..7) via cp.async ----
    #pragma unroll
    for (int i = 0; i < 2; ++i) {                // 128 rows * 8 chunks / 512 thr
        int c = tid + i * NTHREADS;
        int row = c >> 3, ch = c & 7;
        CP_ASYNC16(sAu + row * SROW + ch * 16, gA + row * DD + ch * 8);
    }
    #pragma unroll
    for (int i = 0; i < 4; ++i) {                // 256 rows * 8 chunks / 512 thr
        int c = tid + i * NTHREADS;
        int row = c >> 3, ch = c & 7;
        CP_ASYNC16(sBu + row * SROW + ch * 16, gB + row * DD + ch * 8);
    }
    CP_ASYNC_COMMIT();
    // ---- stage 1: K cols [64,128) (chunks 8..15) ----
    #pragma unroll
    for (int i = 0; i < 2; ++i) {
        int c = tid + i * NTHREADS;
        int row = c >> 3, ch = (c & 7) + 8;
        CP_ASYNC16(sAu + row * SROW + ch * 16, gA + row * DD + ch * 8);
    }
    #pragma unroll
    for (int i = 0; i < 4; ++i) {
        int c = tid + i * NTHREADS;
        int row = c >> 3, ch = (c & 7) + 8;
        CP_ASYNC16(sBu + row * SROW + ch * 16, gB + row * DD + ch * 8);
    }
    CP_ASYNC_COMMIT();

    // ---- warp GEMM ----
    float acc[4][4][4];
    #pragma unroll
    for (int i = 0; i < 4; ++i)
        #pragma unroll
        for (int j = 0; j < 4; ++j)
            #pragma unroll
            for (int k = 0; k < 4; ++k) acc[i][j][k] = 0.0f;

    const char* aw = sA + (warp_m * 64 + g) * SROW + t4 * 4;
    const char* bw = sB + (warp_n * 32 + g) * SROW + t4 * 4;

    CP_ASYNC_WAIT(1);                            // stage 0 landed (this thread)
    __syncthreads();                             // block-wide
    gemm_4ksteps(acc, aw, bw, 0);                // K [0,64)

    CP_ASYNC_WAIT(0);                            // stage 1 landed
    __syncthreads();
    gemm_4ksteps(acc, aw, bw, 128);              // K [64,128) = byte offset 128

    // ---- epilogue ----
    // C frag layout: c0,c1 = row g cols {2t,2t+1}; c2,c3 = row g+8 same cols.
    const bool diag_cta = (nt2 == mt);
    const int bi0 = 2 * warp_n, bi1 = 2 * warp_n + 1;
    float p0 = 0.0f, p1 = 0.0f;
    float qv[8];                                  // [2*mtile + half] row sums e0+e1

    #pragma unroll
    for (int mtl = 0; mtl < 4; ++mtl) {
        #pragma unroll
        for (int h = 0; h < 2; ++h) {            // h=0: row g, h=1: row g+8
            const int ci = 2 * h;
            float m0 = fmaxf(fmaxf(acc[mtl][0][ci], acc[mtl][0][ci+1]),
                             fmaxf(acc[mtl][1][ci], acc[mtl][1][ci+1]));
            float m1 = fmaxf(fmaxf(acc[mtl][2][ci], acc[mtl][2][ci+1]),
                             fmaxf(acc[mtl][3][ci], acc[mtl][3][ci+1]));
            // reduce over the 4 t-lanes (cols within n8 tiles)
            m0 = fmaxf(m0, __shfl_xor_sync(0xffffffffu, m0, 1));
            m0 = fmaxf(m0, __shfl_xor_sync(0xffffffffu, m0, 2));
            m1 = fmaxf(m1, __shfl_xor_sync(0xffffffffu, m1, 1));
            m1 = fmaxf(m1, __shfl_xor_sync(0xffffffffu, m1, 2));
            float e0 = __expf(m0);               // TEMPERATURE = 1
            float e1 = __expf(m1);
            qv[2 * mtl + h] = e0 + e1;
            p0 += e0; p1 += e1;
            if (diag_cta && t4 == 0) {
                int row_local = warp_m * 64 + mtl * 16 + g + 8 * h;
                int grp = row_local >> 3;        // txt batch group within tile
                if (grp == bi0) g_diag[TILE_M * mt + row_local] = m0;
                if (grp == bi1) g_diag[TILE_M * mt + row_local] = m1;
            }
        }
    }

    // den_i2t partials: values identical across t4 lanes; reduce across g only.
    p0 += __shfl_xor_sync(0xffffffffu, p0, 4);
    p0 += __shfl_xor_sync(0xffffffffu, p0, 8);
    p0 += __shfl_xor_sync(0xffffffffu, p0, 16);
    p1 += __shfl_xor_sync(0xffffffffu, p1, 4);
    p1 += __shfl_xor_sync(0xffffffffu, p1, 8);
    p1 += __shfl_xor_sync(0xffffffffu, p1, 16);
    if (lane == 0) { red_p[bi0][warp_m] = p0; red_p[bi1][warp_m] = p1; }

    // den_t2i partials per row (t4==0 lanes hold distinct rows)
    if (t4 == 0) {
        #pragma unroll
        for (int idx = 0; idx < 8; ++idx) {
            int row_local = warp_m * 64 + (idx >> 1) * 16 + g + 8 * (idx & 1);
            red_q[warp_n][row_local] = qv[idx];
        }
    }
    __syncthreads();

    if (tid < 128) {
        float q = 0.0f;
        #pragma unroll
        for (int wn = 0; wn < 8; ++wn) q += red_q[wn][tid];
        g_Q[(size_t)nt2 * TXT_ROWS + TILE_M * mt + tid] = q;
    }
    if (tid < 16) {
        g_P[mt * BATCH + 16 * nt2 + tid] = red_p[tid][0] + red_p[tid][1];
    }
}

// ---------------- kernel 3a: parallel partial reduction (32 CTAs, deterministic) ----------------
__global__ __launch_bounds__(256)
void finalize_partial_kernel()
{
    const int c = blockIdx.x;          // [0,32)
    const int t = threadIdx.x;         // [0,256)
    double acc = 0.0;

    if (t < 128) {
        const int txt = 128 * c + t;
        float den = 0.0f;
        #pragma unroll 8
        for (int nt = 0; nt < NT2_TILES; ++nt) den += g_Q[(size_t)nt * TXT_ROWS + txt];
        // + log den_t2i[b,t]  and  -(1 + 1/T) * S[b,b,t]  (i2t mean over T=8 -> 1/8)
        acc = (double)logf(den) - 1.125 * (double)g_diag[txt];
    } else if (t < 128 + 16) {
        const int bi = 16 * c + (t - 128);
        float den = 0.0f;
        #pragma unroll 8
        for (int mtl = 0; mtl < MT_TILES; ++mtl) den += g_P[mtl * BATCH + bi];
        acc = (double)logf(den);
    }

    #pragma unroll
    for (int off = 16; off >= 1; off >>= 1)
        acc += __shfl_xor_sync(0xffffffffu, acc, off);
    __shared__ double wsum[8];
    if ((t & 31) == 0) wsum[t >> 5] = acc;
    __syncthreads();
    if (t == 0) {
        double s = 0.0;
        #pragma unroll
        for (int i = 0; i < 8; ++i) s += wsum[i];
        g_part[c] = s;
    }
}

// ---------------- kernel 3b: final 32-value sum -> scalar loss ----------------
__global__ __launch_bounds__(32)
void finalize_final_kernel(float* __restrict__ out, int out_size)
{
    const int t = threadIdx.x;
    double s = g_part[t];
    #pragma unroll
    for (int off = 16; off >= 1; off >>= 1)
        s += __shfl_xor_sync(0xffffffffu, s, off);
    if (t == 0) {
        float loss = (float)s;
        for (int i = 0; i < out_size; ++i) out[i] = loss;
    }
}

// ---------------- launch ----------------
extern "C" void kernel_launch(void* const* d_in, const int* in_sizes, int n_in,
                              void* d_out, int out_size)
{
    const float* img  = (const float*)d_in[0];
    const float* text = (const float*)d_in[1];
    if (n_in >= 2 && in_sizes[0] == TXT_ROWS * DD) {  // safety: order by size
        img  = (const float*)d_in[1];
        text = (const float*)d_in[0];
    }

    cudaFuncSetAttribute(gemm_epilogue_kernel,
                         cudaFuncAttributeMaxDynamicSharedMemorySize, SMEM_TILES);

    norm_kernel<<<(IMG_ROWS + TXT_ROWS) / 8, 256>>>(img, text);
    gemm_epilogue_kernel<<<dim3(NT2_TILES, MT_TILES), NTHREADS, SMEM_TILES>>>();
    finalize_partial_kernel<<<MT_TILES, 256>>>();
    finalize_final_kernel<<<1, 32>>>((float*)d_out, out_size);
}

// round 12
// speedup vs baseline: 1.0253x; 1.0253x over previous
#include <cuda_runtime.h>
#include <cuda_bf16.h>
#include <cstdint>

// ---------------- problem dims ----------------
#define BATCH    512
#define ZI       16
#define TT       8
#define DD       128
#define IMG_ROWS (BATCH*ZI)   // 8192 img vectors
#define TXT_ROWS (BATCH*TT)   // 4096 text vectors

// GEMM: C[txt][img] ; CTA tile: M = 128 txt rows, N = 256 img rows, K = 128
#define TILE_M   128
#define TILE_N   256
#define MT_TILES  (TXT_ROWS/TILE_M)   // 32
#define NT2_TILES (IMG_ROWS/TILE_N)   // 32

#define NTHREADS 512                  // 16 warps: 2 (M) x 8 (N)
// per-warp tile: 64 (M) x 32 (N) -> 4 mtiles (m16) x 4 ntiles (n8), acc = 64 fp32 regs

// smem: row = 128 bf16 = 256 B, padded stride 272 B (68 banks -> ldmatrix row
// addresses land on distinct bank quads -> conflict-free)
#define SROW     272
#define SMEM_A_OFF 0                       // text tile: 128 rows
#define SMEM_B_OFF (128*SROW)              // img tile:  256 rows
#define SMEM_TILES ((128+256)*SROW)        // 104448 B

// ---------------- scratch (device globals; no allocation allowed) ----------------
__device__ __align__(16) __nv_bfloat16 g_imgn [IMG_ROWS*DD];   // 2 MB
__device__ __align__(16) __nv_bfloat16 g_textn[TXT_ROWS*DD];   // 1 MB
__device__ float  g_Q[NT2_TILES*TXT_ROWS];  // den_t2i partials: [nt2][txt]  512 KB
__device__ float  g_P[MT_TILES*BATCH];      // den_i2t partials: [mt][bi]    64 KB
__device__ float  g_diag[TXT_ROWS];         // S[b,b,t] at txt=b*8+t         16 KB
__device__ double g_part[MT_TILES];         // per-CTA partial loss sums     256 B
__device__ int    g_cnt = 0;                // ticket counter (reset each run)

// ---------------- helpers ----------------
__device__ __forceinline__ uint32_t smem_u32(const void* p) {
    uint32_t a;
    asm("{ .reg .u64 tmp; cvta.to.shared.u64 tmp, %1; cvt.u32.u64 %0, tmp; }"
        : "=r"(a) : "l"(p));
    return a;
}
// cp.async 16B, L2-only (.cg) — sm_80 base PTX, valid at .target sm_103
#define CP_ASYNC16(saddr, gptr) \
    asm volatile("cp.async.cg.shared.global [%0], [%1], 16;" \
        :: "r"(saddr), "l"(__cvta_generic_to_global(gptr)) : "memory")
#define CP_ASYNC_COMMIT() asm volatile("cp.async.commit_group;" ::: "memory")
#define CP_ASYNC_WAIT(n)  asm volatile("cp.async.wait_group %0;" :: "n"(n) : "memory")

// ldmatrix (sm_75 base PTX): 8x8 b16 tiles from shared memory
#define LDSM_X4(r0, r1, r2, r3, addr) \
    asm volatile("ldmatrix.sync.aligned.m8n8.x4.shared.b16 {%0,%1,%2,%3}, [%4];" \
        : "=r"(r0), "=r"(r1), "=r"(r2), "=r"(r3) : "r"(addr))
#define LDSM_X2(r0, r1, addr) \
    asm volatile("ldmatrix.sync.aligned.m8n8.x2.shared.b16 {%0,%1}, [%2];" \
        : "=r"(r0), "=r"(r1) : "r"(addr))

// ---------------- kernel 1: L2-normalize rows, write bf16 ----------------
__global__ __launch_bounds__(256)
void norm_kernel(const float* __restrict__ img, const float* __restrict__ text)
{
    int gw   = (blockIdx.x * blockDim.x + threadIdx.x) >> 5;  // global warp = row
    int lane = threadIdx.x & 31;
    if (gw >= IMG_ROWS + TXT_ROWS) return;

    const float* src;
    __nv_bfloat16* dst;
    if (gw < IMG_ROWS) { src = img  + (size_t)gw * DD;            dst = g_imgn  + (size_t)gw * DD; }
    else               { src = text + (size_t)(gw - IMG_ROWS)*DD; dst = g_textn + (size_t)(gw - IMG_ROWS)*DD; }

    float4 v = reinterpret_cast<const float4*>(src)[lane];
    float ss = v.x*v.x + v.y*v.y + v.z*v.z + v.w*v.w;
    #pragma unroll
    for (int off = 16; off >= 1; off >>= 1)
        ss += __shfl_xor_sync(0xffffffffu, ss, off);
    float inv = 1.0f / fmaxf(sqrtf(ss), 1e-12f);

    __nv_bfloat162 p0 = __floats2bfloat162_rn(v.x * inv, v.y * inv);
    __nv_bfloat162 p1 = __floats2bfloat162_rn(v.z * inv, v.w * inv);
    reinterpret_cast<__nv_bfloat162*>(dst)[2*lane + 0] = p0;
    reinterpret_cast<__nv_bfloat162*>(dst)[2*lane + 1] = p1;
}

// ---------------- bf16 warp MMA: m16n8k16, row.col, fp32 acc ----------------
__device__ __forceinline__ void mma_16816(float* c, uint32_t a0, uint32_t a1,
                                          uint32_t a2, uint32_t a3,
                                          uint32_t b0, uint32_t b1)
{
    asm volatile(
        "mma.sync.aligned.m16n8k16.row.col.f32.bf16.bf16.f32 "
        "{%0,%1,%2,%3}, {%4,%5,%6,%7}, {%8,%9}, {%0,%1,%2,%3};\n"
        : "+f"(c[0]), "+f"(c[1]), "+f"(c[2]), "+f"(c[3])
        : "r"(a0), "r"(a1), "r"(a2), "r"(a3), "r"(b0), "r"(b1));
}

// 4 K-steps (64 bf16 of K) from byte offset kbase, using ldmatrix fragment loads.
// aAddr: this lane's A ldmatrix address for mtl=0, kbase=0
//   = sA + (warp_m*64 + (lane&7) + 8*((lane>>3)&1))*SROW + 16*(lane>>4)
//   x4 -> {a0,a1,a2,a3} = {(rows g,k0-7),(rows g+8,k0-7),(g,k8-15),(g+8,k8-15)}
// bAddr: this lane's B ldmatrix address for nt=0, kbase=0 (lanes 0-15 used)
//   = sB + (warp_n*32 + (lane&7))*SROW + 16*((lane>>3)&1)
//   x2 -> {b0,b1} = {(n rows, k0-7),(n rows, k8-15)}  (rows = img vectors, cols = k)
__device__ __forceinline__ void gemm_4ksteps(float (*acc)[4][4],
                                             uint32_t aAddr, uint32_t bAddr, int kbase)
{
    #pragma unroll
    for (int ks = 0; ks < 4; ++ks) {
        const int ko = kbase + ks * 32;          // 16 bf16 = 32 bytes per K-step
        uint32_t b0[4], b1[4];
        #pragma unroll
        for (int nt = 0; nt < 4; ++nt)
            LDSM_X2(b0[nt], b1[nt], bAddr + nt * (8 * SROW) + ko);
        #pragma unroll
        for (int mtl = 0; mtl < 4; ++mtl) {
            uint32_t a0, a1, a2, a3;
            LDSM_X4(a0, a1, a2, a3, aAddr + mtl * (16 * SROW) + ko);
            #pragma unroll
            for (int nt = 0; nt < 4; ++nt)
                mma_16816(acc[mtl][nt], a0, a1, a2, a3, b0[nt], b1[nt]);
        }
    }
}

// ---------------- kernel 2: fused GEMM (HMMA) + max/exp/reduce epilogue ----------------
__global__ __launch_bounds__(NTHREADS)
void gemm_epilogue_kernel()
{
    extern __shared__ char smem[];
    char* sA = smem + SMEM_A_OFF;
    char* sB = smem + SMEM_B_OFF;
    __shared__ float red_q[8][128];   // [warp_n][local txt row] partial den_t2i
    __shared__ float red_p[16][2];    // [local bi][warp_m] partial den_i2t

    const int tid  = threadIdx.x;
    const int wid  = tid >> 5;
    const int lane = tid & 31;
    const int g    = lane >> 2;       // 0..7
    const int t4   = lane & 3;        // 0..3
    const int warp_m = wid >> 3;      // 0..1  (64-row half)
    const int warp_n = wid & 7;       // 0..7  (32-col slice = 2 bi-groups)
    const int nt2 = blockIdx.x;       // img tile  [0,32)
    const int mt  = blockIdx.y;       // text tile [0,32)

    const __nv_bfloat16* gA = g_textn + (size_t)(TILE_M * mt) * DD;
    const __nv_bfloat16* gB = g_imgn  + (size_t)(TILE_N * nt2) * DD;
    const uint32_t sAu = smem_u32(sA);
    const uint32_t sBu = smem_u32(sB);

    // ---- stage 0: K cols [0,64) (chunks 0..7) via cp.async ----
    #pragma unroll
    for (int i = 0; i < 2; ++i) {                // 128 rows * 8 chunks / 512 thr
        int c = tid + i * NTHREADS;
        int row = c >> 3, ch = c & 7;
        CP_ASYNC16(sAu + row * SROW + ch * 16, gA + row * DD + ch * 8);
    }
    #pragma unroll
    for (int i = 0; i < 4; ++i) {                // 256 rows * 8 chunks / 512 thr
        int c = tid + i * NTHREADS;
        int row = c >> 3, ch = c & 7;
        CP_ASYNC16(sBu + row * SROW + ch * 16, gB + row * DD + ch * 8);
    }
    CP_ASYNC_COMMIT();
    // ---- stage 1: K cols [64,128) (chunks 8..15) ----
    #pragma unroll
    for (int i = 0; i < 2; ++i) {
        int c = tid + i * NTHREADS;
        int row = c >> 3, ch = (c & 7) + 8;
        CP_ASYNC16(sAu + row * SROW + ch * 16, gA + row * DD + ch * 8);
    }
    #pragma unroll
    for (int i = 0; i < 4; ++i) {
        int c = tid + i * NTHREADS;
        int row = c >> 3, ch = (c & 7) + 8;
        CP_ASYNC16(sBu + row * SROW + ch * 16, gB + row * DD + ch * 8);
    }
    CP_ASYNC_COMMIT();

    // ---- warp GEMM ----
    float acc[4][4][4];
    #pragma unroll
    for (int i = 0; i < 4; ++i)
        #pragma unroll
        for (int j = 0; j < 4; ++j)
            #pragma unroll
            for (int k = 0; k < 4; ++k) acc[i][j][k] = 0.0f;

    // per-lane ldmatrix base addresses
    const uint32_t aAddr = sAu
        + (warp_m * 64 + (lane & 7) + 8 * ((lane >> 3) & 1)) * SROW
        + 16 * (lane >> 4);
    const uint32_t bAddr = sBu
        + (warp_n * 32 + (lane & 7)) * SROW
        + 16 * ((lane >> 3) & 1);

    CP_ASYNC_WAIT(1);                            // stage 0 landed (this thread)
    __syncthreads();                             // block-wide
    gemm_4ksteps(acc, aAddr, bAddr, 0);          // K [0,64)

    CP_ASYNC_WAIT(0);                            // stage 1 landed
    __syncthreads();
    gemm_4ksteps(acc, aAddr, bAddr, 128);        // K [64,128) = byte offset 128

    // ---- epilogue ----
    // C frag layout: c0,c1 = row g cols {2t,2t+1}; c2,c3 = row g+8 same cols.
    const bool diag_cta = (nt2 == mt);
    const int bi0 = 2 * warp_n, bi1 = 2 * warp_n + 1;
    float p0 = 0.0f, p1 = 0.0f;
    float qv[8];                                  // [2*mtile + half] row sums e0+e1

    #pragma unroll
    for (int mtl = 0; mtl < 4; ++mtl) {
        #pragma unroll
        for (int h = 0; h < 2; ++h) {            // h=0: row g, h=1: row g+8
            const int ci = 2 * h;
            float m0 = fmaxf(fmaxf(acc[mtl][0][ci], acc[mtl][0][ci+1]),
                             fmaxf(acc[mtl][1][ci], acc[mtl][1][ci+1]));
            float m1 = fmaxf(fmaxf(acc[mtl][2][ci], acc[mtl][2][ci+1]),
                             fmaxf(acc[mtl][3][ci], acc[mtl][3][ci+1]));
            // reduce over the 4 t-lanes (cols within n8 tiles)
            m0 = fmaxf(m0, __shfl_xor_sync(0xffffffffu, m0, 1));
            m0 = fmaxf(m0, __shfl_xor_sync(0xffffffffu, m0, 2));
            m1 = fmaxf(m1, __shfl_xor_sync(0xffffffffu, m1, 1));
            m1 = fmaxf(m1, __shfl_xor_sync(0xffffffffu, m1, 2));
            float e0 = __expf(m0);               // TEMPERATURE = 1
            float e1 = __expf(m1);
            qv[2 * mtl + h] = e0 + e1;
            p0 += e0; p1 += e1;
            if (diag_cta && t4 == 0) {
                int row_local = warp_m * 64 + mtl * 16 + g + 8 * h;
                int grp = row_local >> 3;        // txt batch group within tile
                if (grp == bi0) g_diag[TILE_M * mt + row_local] = m0;
                if (grp == bi1) g_diag[TILE_M * mt + row_local] = m1;
            }
        }
    }

    // den_i2t partials: values identical across t4 lanes; reduce across g only.
    p0 += __shfl_xor_sync(0xffffffffu, p0, 4);
    p0 += __shfl_xor_sync(0xffffffffu, p0, 8);
    p0 += __shfl_xor_sync(0xffffffffu, p0, 16);
    p1 += __shfl_xor_sync(0xffffffffu, p1, 4);
    p1 += __shfl_xor_sync(0xffffffffu, p1, 8);
    p1 += __shfl_xor_sync(0xffffffffu, p1, 16);
    if (lane == 0) { red_p[bi0][warp_m] = p0; red_p[bi1][warp_m] = p1; }

    // den_t2i partials per row (t4==0 lanes hold distinct rows)
    if (t4 == 0) {
        #pragma unroll
        for (int idx = 0; idx < 8; ++idx) {
            int row_local = warp_m * 64 + (idx >> 1) * 16 + g + 8 * (idx & 1);
            red_q[warp_n][row_local] = qv[idx];
        }
    }
    __syncthreads();

    if (tid < 128) {
        float q = 0.0f;
        #pragma unroll
        for (int wn = 0; wn < 8; ++wn) q += red_q[wn][tid];
        g_Q[(size_t)nt2 * TXT_ROWS + TILE_M * mt + tid] = q;
    }
    if (tid < 16) {
        g_P[mt * BATCH + 16 * nt2 + tid] = red_p[tid][0] + red_p[tid][1];
    }
}

// ---------------- kernel 3: fused finalize (32 CTAs + last-CTA final sum) ----------------
__global__ __launch_bounds__(256)
void finalize_kernel(float* __restrict__ out, int out_size)
{
    const int c = blockIdx.x;          // [0,32)
    const int t = threadIdx.x;         // [0,256)
    double acc = 0.0;

    if (t < 128) {
        const int txt = 128 * c + t;
        float den = 0.0f;
        #pragma unroll 8
        for (int nt = 0; nt < NT2_TILES; ++nt) den += g_Q[(size_t)nt * TXT_ROWS + txt];
        // + log den_t2i[b,t]  and  -(1 + 1/T) * S[b,b,t]  (i2t mean over T=8 -> 1/8)
        acc = (double)logf(den) - 1.125 * (double)g_diag[txt];
    } else if (t < 128 + 16) {
        const int bi = 16 * c + (t - 128);
        float den = 0.0f;
        #pragma unroll 8
        for (int mtl = 0; mtl < MT_TILES; ++mtl) den += g_P[mtl * BATCH + bi];
        acc = (double)logf(den);
    }

    // deterministic block reduce -> g_part[c]
    #pragma unroll
    for (int off = 16; off >= 1; off >>= 1)
        acc += __shfl_xor_sync(0xffffffffu, acc, off);
    __shared__ double wsum[8];
    __shared__ int islast;
    if ((t & 31) == 0) wsum[t >> 5] = acc;
    __syncthreads();
    if (t == 0) {
        double s = 0.0;
        #pragma unroll
        for (int i = 0; i < 8; ++i) s += wsum[i];
        g_part[c] = s;
        __threadfence();                       // publish before ticket
        islast = (atomicAdd(&g_cnt, 1) == MT_TILES - 1);
    }
    __syncthreads();

    // last CTA: fixed-order final sum (bitwise deterministic), write out, reset ticket
    if (islast && t < 32) {
        double s = g_part[t];
        #pragma unroll
        for (int off = 16; off >= 1; off >>= 1)
            s += __shfl_xor_sync(0xffffffffu, s, off);
        if (t == 0) {
            float loss = (float)s;
            for (int i = 0; i < out_size; ++i) out[i] = loss;
            g_cnt = 0;                         // graph-replay safe reset
        }
    }
}

// ---------------- launch ----------------
extern "C" void kernel_launch(void* const* d_in, const int* in_sizes, int n_in,
                              void* d_out, int out_size)
{
    const float* img  = (const float*)d_in[0];
    const float* text = (const float*)d_in[1];
    if (n_in >= 2 && in_sizes[0] == TXT_ROWS * DD) {  // safety: order by size
        img  = (const float*)d_in[1];
        text = (const float*)d_in[0];
    }

    cudaFuncSetAttribute(gemm_epilogue_kernel,
                         cudaFuncAttributeMaxDynamicSharedMemorySize, SMEM_TILES);

    norm_kernel<<<(IMG_ROWS + TXT_ROWS) / 8, 256>>>(img, text);
    gemm_epilogue_kernel<<<dim3(NT2_TILES, MT_TILES), NTHREADS, SMEM_TILES>>>();
    finalize_kernel<<<MT_TILES, 256>>>((float*)d_out, out_size);
}